// round 1
// baseline (speedup 1.0000x reference)
#include <cuda_runtime.h>
#include <math.h>

// DisneyNet: pointwise shading eval with table gathers.
// out[i] = (x, y) per the JAX reference.

static __device__ __forceinline__ float triw(float x) {
    // 2*|x/2 - floor(x/2 + 0.5)|
    return 2.0f * fabsf(0.5f * x - floorf(0.5f * x + 0.5f));
}

static __device__ __forceinline__ float clip01(float x) {
    return fminf(fmaxf(x, 0.0f), 1.0f - 1e-6f);
}

// 2D bilinear lookup, table shape (U, V, C), coords map u->dim0, v->dim1.
template <int U, int V, int C, bool NORM>
static __device__ __forceinline__ void grid2d_bilin(const float* __restrict__ t,
                                                    float cu, float cv,
                                                    float* __restrict__ o) {
    float u = clip01(cu) * (float)(U - 1);
    float v = clip01(cv) * (float)(V - 1);
    float u0f = floorf(u), v0f = floorf(v);
    float fu = u - u0f, fv = v - v0f;
    int u0 = (int)u0f, v0 = (int)v0f;
    int u1 = min(u0 + 1, U - 1), v1 = min(v0 + 1, V - 1);
    float w00 = (1.0f - fu) * (1.0f - fv);
    float w10 = fu * (1.0f - fv);
    float w01 = (1.0f - fu) * fv;
    float w11 = fu * fv;
    const float* p00 = t + (u0 * V + v0) * C;
    const float* p10 = t + (u1 * V + v0) * C;
    const float* p01 = t + (u0 * V + v1) * C;
    const float* p11 = t + (u1 * V + v1) * C;
#pragma unroll
    for (int c = 0; c < C; ++c) {
        float a = p00[c], b = p10[c], d = p01[c], e = p11[c];
        if (NORM) { a = triw(a); b = triw(b); d = triw(d); e = triw(e); }
        o[c] = a * w00 + b * w10 + d * w01 + e * w11;
    }
}

// Specialization for C=4 tables using float4 corner loads (tabLV/tabNHL).
template <int U, int V, bool NORM>
static __device__ __forceinline__ void grid2d_bilin4(const float4* __restrict__ t,
                                                     float cu, float cv,
                                                     float* __restrict__ o) {
    float u = clip01(cu) * (float)(U - 1);
    float v = clip01(cv) * (float)(V - 1);
    float u0f = floorf(u), v0f = floorf(v);
    float fu = u - u0f, fv = v - v0f;
    int u0 = (int)u0f, v0 = (int)v0f;
    int u1 = min(u0 + 1, U - 1), v1 = min(v0 + 1, V - 1);
    float w00 = (1.0f - fu) * (1.0f - fv);
    float w10 = fu * (1.0f - fv);
    float w01 = (1.0f - fu) * fv;
    float w11 = fu * fv;
    float4 a = t[u0 * V + v0];
    float4 b = t[u1 * V + v0];
    float4 d = t[u0 * V + v1];
    float4 e = t[u1 * V + v1];
    if (NORM) {
        a.x = triw(a.x); a.y = triw(a.y); a.z = triw(a.z); a.w = triw(a.w);
        b.x = triw(b.x); b.y = triw(b.y); b.z = triw(b.z); b.w = triw(b.w);
        d.x = triw(d.x); d.y = triw(d.y); d.z = triw(d.z); d.w = triw(d.w);
        e.x = triw(e.x); e.y = triw(e.y); e.z = triw(e.z); e.w = triw(e.w);
    }
    o[0] = a.x * w00 + b.x * w10 + d.x * w01 + e.x * w11;
    o[1] = a.y * w00 + b.y * w10 + d.y * w01 + e.y * w11;
    o[2] = a.z * w00 + b.z * w10 + d.z * w01 + e.z * w11;
    o[3] = a.w * w00 + b.w * w10 + d.w * w01 + e.w * w11;
}

__global__ void __launch_bounds__(256)
disneynet_kernel(const float2* __restrict__ roughNoh,
                 const float2* __restrict__ anisoToh,
                 const float2* __restrict__ nDotLV,
                 const float2* __restrict__ metalLoh,
                 const float2* __restrict__ subCg,
                 const float2* __restrict__ spst,
                 const float2* __restrict__ shst,
                 const float2* __restrict__ lumCs,
                 const float2* __restrict__ tabRAEnc,  // 2048x2048, 2ch
                 const float*  __restrict__ tabCgEnc,  // 2048x1
                 const float*  __restrict__ tabRSEnc,  // 64x64x3
                 const float*  __restrict__ tabRADec,  // 48x48x3
                 const float2* __restrict__ tabCgDec,  // 96x2
                 const float*  __restrict__ tabLVR,    // 32x32x1
                 const float4* __restrict__ tabLV,     // 32x32x4
                 const float4* __restrict__ tabNHL,    // 32x32x4
                 float2* __restrict__ out,
                 int n) {
    int i = blockIdx.x * blockDim.x + threadIdx.x;
    if (i >= n) return;

    const float2 rn = roughNoh[i];
    const float2 at = anisoToh[i];
    const float2 nl = nDotLV[i];
    const float2 ml = metalLoh[i];
    const float2 sc = subCg[i];
    const float2 sp = spst[i];
    const float2 sh = shst[i];
    const float2 lc = lumCs[i];

    // ra = grid2d nearest, normalized, tabRAEnc(2048,2048,2), coords (rn.x, at.x)
    int ui = (int)rintf(clip01(rn.x) * 2047.0f);
    int vi = (int)rintf(clip01(at.x) * 2047.0f);
    float2 raRaw = tabRAEnc[ui * 2048 + vi];
    float ra0 = triw(raRaw.x);
    float ra1 = triw(raRaw.y);

    // cg = grid1d nearest, normalized, tabCgEnc(2048,1), coord sc.y
    int ci = (int)rintf(clip01(sc.y) * 2047.0f);
    float cg0 = triw(tabCgEnc[ci]);

    // rsEnc = grid2d bilinear, normalized, tabRSEnc(64,64,3), coords (rn.x, sc.x)
    float rs[3];
    grid2d_bilin<64, 64, 3, true>(tabRSEnc, rn.x, sc.x, rs);

    const float m = ml.x;
    const float om = 1.0f - m;
    const float cd  = om * lc.x;
    const float cm0 = sp.x * 0.1f * om * sp.y + m * lc.x;
    const float cm1 = sp.x * 0.1f * om * (1.0f - sp.y);
    const float cs0 = sh.x * om * sh.y;
    const float cs1 = sh.x * om * (1.0f - sh.y);
    const float ccv = 0.0625f * lc.y;   // 0.25*0.25*lumCs1

    const float rsCd0 = rs[0] * cd;
    const float rsCd1 = rs[1] * cd;
    const float rsCd2 = rs[2] * cd;

    // raCoefs = grid2d bilinear, NOT normalized, tabRADec(48,48,3), coords (ra0, ra1)
    float raC[3];
    grid2d_bilin<48, 48, 3, false>(tabRADec, ra0, ra1, raC);

    // cgCoefs = grid1d bilinear, NOT normalized, tabCgDec(96,2), coord cg0
    float cgC0, cgC1;
    {
        float u = clip01(cg0) * 95.0f;
        float u0f = floorf(u);
        float fu = u - u0f;
        int u0 = (int)u0f;
        int u1 = min(u0 + 1, 95);
        float2 a = tabCgDec[u0];
        float2 b = tabCgDec[u1];
        cgC0 = a.x * (1.0f - fu) + b.x * fu;
        cgC1 = a.y * (1.0f - fu) + b.y * fu;
    }

    // vTerm = grid2d bilinear, normalized, tabLVR(32,32,1), coords (nl.x*nl.y, ra0)
    float vT[1];
    grid2d_bilin<32, 32, 1, true>(tabLVR, nl.x * nl.y, ra0, vT);

    // nlvCoefs = grid2d bilinear, normalized, tabLV(32,32,4), coords (nl.x, nl.y)
    float nlv[4];
    grid2d_bilin4<32, 32, true>(tabLV, nl.x, nl.y, nlv);

    // nhlCoefs = grid2d bilinear, normalized, tabNHL(32,32,4), coords (ml.y, nl.x)
    float nhl[4];
    grid2d_bilin4<32, 32, true>(tabNHL, ml.y, nl.x, nhl);

    const float noh2 = rn.y * rn.y;
    const float den = raC[0] * at.y * at.y + raC[1] * noh2 + raC[2];
    const float dT = 0.25f / (nl.y * den * den);

    float x = rsCd0 * ml.y * nlv[1]
            + rsCd1 * nlv[2]
            + rsCd2 * nlv[3]
            + cm0 * vT[0] * nhl[2] * dT
            + cs0 * nhl[0];

    float y = ((1.0f - cm1) * nhl[3] + cm1) * vT[0] * dT
            + cs1 * nhl[0]
            + ccv * nhl[1] * nlv[0] / (nl.y * (cgC0 * noh2 + cgC1));

    out[i] = make_float2(x, y);
}

extern "C" void kernel_launch(void* const* d_in, const int* in_sizes, int n_in,
                              void* d_out, int out_size) {
    // Input order per setup_inputs:
    // 0 roughNoh 1 anisoToh 2 nDotLV 3 tDotLV(unused) 4 metalLoh 5 subCg
    // 6 spst 7 shst 8 lumCs 9 tabRAEnc 10 tabCgEnc 11 tabRSEnc 12 tabRADec
    // 13 tabCgDec 14 tabLVR 15 tabLV 16 tabNHL
    const int n = in_sizes[0] / 2;  // (N,2) float32
    const int threads = 256;
    const int blocks = (n + threads - 1) / threads;
    disneynet_kernel<<<blocks, threads>>>(
        (const float2*)d_in[0],
        (const float2*)d_in[1],
        (const float2*)d_in[2],
        (const float2*)d_in[4],
        (const float2*)d_in[5],
        (const float2*)d_in[6],
        (const float2*)d_in[7],
        (const float2*)d_in[8],
        (const float2*)d_in[9],
        (const float*)d_in[10],
        (const float*)d_in[11],
        (const float*)d_in[12],
        (const float2*)d_in[13],
        (const float*)d_in[14],
        (const float4*)d_in[15],
        (const float4*)d_in[16],
        (float2*)d_out,
        n);
}

// round 2
// speedup vs baseline: 1.4344x; 1.4344x over previous
#include <cuda_runtime.h>
#include <math.h>

// DisneyNet: pointwise shading eval with table gathers.
// Persistent kernel: small LUTs staged (pre-normalized) into shared memory,
// big tabRAEnc gathered from L2.

static __device__ __forceinline__ float triw(float x) {
    // 2*|x/2 - floor(x/2 + 0.5)|
    return 2.0f * fabsf(0.5f * x - floorf(0.5f * x + 0.5f));
}

static __device__ __forceinline__ float clip01(float x) {
    return fminf(fmaxf(x, 0.0f), 1.0f - 1e-6f);
}

// ---- shared memory layout (floats) ----
// sRS   : 64*64*4  = 16384   tabRSEnc, triw-applied, padded C3->C4
// sRA   : 48*48*4  =  9216   tabRADec, padded C3->C4
// sLV   : 32*32*4  =  4096   tabLV, triw-applied
// sNHL  : 32*32*4  =  4096   tabNHL, triw-applied
// sLVR  : 32*32    =  1024   tabLVR, triw-applied
// sCgE  : 2048     =  2048   tabCgEnc, triw-applied
// sCgD  : 96*2     =   192   tabCgDec
static constexpr int OFF_RS  = 0;
static constexpr int OFF_RA  = OFF_RS  + 64 * 64 * 4;
static constexpr int OFF_LV  = OFF_RA  + 48 * 48 * 4;
static constexpr int OFF_NHL = OFF_LV  + 32 * 32 * 4;
static constexpr int OFF_LVR = OFF_NHL + 32 * 32 * 4;
static constexpr int OFF_CGE = OFF_LVR + 32 * 32;
static constexpr int OFF_CGD = OFF_CGE + 2048;
static constexpr int SMEM_FLOATS = OFF_CGD + 96 * 2;
static constexpr int SMEM_BYTES = SMEM_FLOATS * 4;   // 148224 B

// Bilinear fetch from a padded-C4 smem table, returns 4 channels.
template <int U, int V>
static __device__ __forceinline__ float4 bilin4_smem(const float* __restrict__ s,
                                                     float cu, float cv) {
    float u = clip01(cu) * (float)(U - 1);
    float v = clip01(cv) * (float)(V - 1);
    float u0f = floorf(u), v0f = floorf(v);
    float fu = u - u0f, fv = v - v0f;
    int u0 = (int)u0f, v0 = (int)v0f;
    int u1 = min(u0 + 1, U - 1), v1 = min(v0 + 1, V - 1);
    const float4* p = (const float4*)s;
    float4 a = p[u0 * V + v0];
    float4 b = p[u1 * V + v0];
    float4 c = p[u0 * V + v1];
    float4 d = p[u1 * V + v1];
    float w00 = (1.0f - fu) * (1.0f - fv);
    float w10 = fu * (1.0f - fv);
    float w01 = (1.0f - fu) * fv;
    float w11 = fu * fv;
    float4 o;
    o.x = a.x * w00 + b.x * w10 + c.x * w01 + d.x * w11;
    o.y = a.y * w00 + b.y * w10 + c.y * w01 + d.y * w11;
    o.z = a.z * w00 + b.z * w10 + c.z * w01 + d.z * w11;
    o.w = a.w * w00 + b.w * w10 + c.w * w01 + d.w * w11;
    return o;
}

// Bilinear fetch from a scalar (C=1) smem table.
template <int U, int V>
static __device__ __forceinline__ float bilin1_smem(const float* __restrict__ s,
                                                    float cu, float cv) {
    float u = clip01(cu) * (float)(U - 1);
    float v = clip01(cv) * (float)(V - 1);
    float u0f = floorf(u), v0f = floorf(v);
    float fu = u - u0f, fv = v - v0f;
    int u0 = (int)u0f, v0 = (int)v0f;
    int u1 = min(u0 + 1, U - 1), v1 = min(v0 + 1, V - 1);
    float a = s[u0 * V + v0];
    float b = s[u1 * V + v0];
    float c = s[u0 * V + v1];
    float d = s[u1 * V + v1];
    return a * (1.0f - fu) * (1.0f - fv) + b * fu * (1.0f - fv)
         + c * (1.0f - fu) * fv + d * fu * fv;
}

__global__ void __launch_bounds__(1024, 1)
disneynet_kernel(const float2* __restrict__ roughNoh,
                 const float2* __restrict__ anisoToh,
                 const float2* __restrict__ nDotLV,
                 const float2* __restrict__ metalLoh,
                 const float2* __restrict__ subCg,
                 const float2* __restrict__ spst,
                 const float2* __restrict__ shst,
                 const float2* __restrict__ lumCs,
                 const float2* __restrict__ tabRAEnc,  // 2048x2048, 2ch (global, L2)
                 const float*  __restrict__ tabCgEnc,  // 2048x1
                 const float*  __restrict__ tabRSEnc,  // 64x64x3
                 const float*  __restrict__ tabRADec,  // 48x48x3
                 const float2* __restrict__ tabCgDec,  // 96x2
                 const float*  __restrict__ tabLVR,    // 32x32x1
                 const float4* __restrict__ tabLV,     // 32x32x4
                 const float4* __restrict__ tabNHL,    // 32x32x4
                 float2* __restrict__ out,
                 int n) {
    extern __shared__ float smem[];
    float* sRS  = smem + OFF_RS;
    float* sRA  = smem + OFF_RA;
    float* sLV  = smem + OFF_LV;
    float* sNHL = smem + OFF_NHL;
    float* sLVR = smem + OFF_LVR;
    float* sCgE = smem + OFF_CGE;
    float* sCgD = smem + OFF_CGD;

    const int tid = threadIdx.x;
    const int nthr = blockDim.x;

    // ---- stage tables (pre-normalize where the reference does) ----
    for (int idx = tid; idx < 64 * 64; idx += nthr) {
        const float* src = tabRSEnc + idx * 3;
        float4 v = make_float4(triw(src[0]), triw(src[1]), triw(src[2]), 0.0f);
        *(float4*)(sRS + idx * 4) = v;
    }
    for (int idx = tid; idx < 48 * 48; idx += nthr) {
        const float* src = tabRADec + idx * 3;
        float4 v = make_float4(src[0], src[1], src[2], 0.0f);
        *(float4*)(sRA + idx * 4) = v;
    }
    for (int idx = tid; idx < 32 * 32; idx += nthr) {
        float4 v = tabLV[idx];
        *(float4*)(sLV + idx * 4) =
            make_float4(triw(v.x), triw(v.y), triw(v.z), triw(v.w));
        float4 w = tabNHL[idx];
        *(float4*)(sNHL + idx * 4) =
            make_float4(triw(w.x), triw(w.y), triw(w.z), triw(w.w));
        sLVR[idx] = triw(tabLVR[idx]);
    }
    for (int idx = tid; idx < 2048; idx += nthr) {
        sCgE[idx] = triw(tabCgEnc[idx]);
    }
    for (int idx = tid; idx < 96; idx += nthr) {
        float2 v = tabCgDec[idx];
        sCgD[idx * 2]     = v.x;
        sCgD[idx * 2 + 1] = v.y;
    }
    __syncthreads();

    const int stride = gridDim.x * nthr;
    for (int i = blockIdx.x * nthr + tid; i < n; i += stride) {
        const float2 rn = roughNoh[i];
        const float2 at = anisoToh[i];
        const float2 nl = nDotLV[i];
        const float2 ml = metalLoh[i];
        const float2 sc = subCg[i];
        const float2 sp = spst[i];
        const float2 sh = shst[i];
        const float2 lc = lumCs[i];

        // ra = nearest, normalized, tabRAEnc(2048,2048,2), coords (rn.x, at.x)
        int ui = (int)rintf(clip01(rn.x) * 2047.0f);
        int vi = (int)rintf(clip01(at.x) * 2047.0f);
        float2 raRaw = __ldg(tabRAEnc + (ui * 2048 + vi));
        float ra0 = triw(raRaw.x);
        float ra1 = triw(raRaw.y);

        // cg = nearest, normalized (pre-applied), tabCgEnc
        int ci = (int)rintf(clip01(sc.y) * 2047.0f);
        float cg0 = sCgE[ci];

        // rsEnc = bilinear, normalized (pre-applied), coords (rn.x, sc.x)
        float4 rs = bilin4_smem<64, 64>(sRS, rn.x, sc.x);

        const float m = ml.x;
        const float om = 1.0f - m;
        const float cd  = om * lc.x;
        const float cm0 = sp.x * 0.1f * om * sp.y + m * lc.x;
        const float cm1 = sp.x * 0.1f * om * (1.0f - sp.y);
        const float cs0 = sh.x * om * sh.y;
        const float cs1 = sh.x * om * (1.0f - sh.y);
        const float ccv = 0.0625f * lc.y;

        const float rsCd0 = rs.x * cd;
        const float rsCd1 = rs.y * cd;
        const float rsCd2 = rs.z * cd;

        // raCoefs = bilinear, not normalized, coords (ra0, ra1)
        float4 raC = bilin4_smem<48, 48>(sRA, ra0, ra1);

        // cgCoefs = 1D bilinear, not normalized, coord cg0
        float cgC0, cgC1;
        {
            float u = clip01(cg0) * 95.0f;
            float u0f = floorf(u);
            float fu = u - u0f;
            int u0 = (int)u0f;
            int u1 = min(u0 + 1, 95);
            float ax = sCgD[u0 * 2], ay = sCgD[u0 * 2 + 1];
            float bx = sCgD[u1 * 2], by = sCgD[u1 * 2 + 1];
            cgC0 = ax * (1.0f - fu) + bx * fu;
            cgC1 = ay * (1.0f - fu) + by * fu;
        }

        // vTerm = bilinear, normalized (pre-applied), coords (nl.x*nl.y, ra0)
        float vT = bilin1_smem<32, 32>(sLVR, nl.x * nl.y, ra0);

        // nlvCoefs = bilinear, normalized (pre-applied), coords (nl.x, nl.y)
        float4 nlv = bilin4_smem<32, 32>(sLV, nl.x, nl.y);

        // nhlCoefs = bilinear, normalized (pre-applied), coords (ml.y, nl.x)
        float4 nhl = bilin4_smem<32, 32>(sNHL, ml.y, nl.x);

        const float noh2 = rn.y * rn.y;
        const float den = raC.x * at.y * at.y + raC.y * noh2 + raC.z;
        const float dT = __fdividef(0.25f, nl.y * den * den);

        float x = rsCd0 * ml.y * nlv.y
                + rsCd1 * nlv.z
                + rsCd2 * nlv.w
                + cm0 * vT * nhl.z * dT
                + cs0 * nhl.x;

        float y = ((1.0f - cm1) * nhl.w + cm1) * vT * dT
                + cs1 * nhl.x
                + ccv * nhl.y * nlv.x * __fdividef(1.0f, nl.y * (cgC0 * noh2 + cgC1));

        out[i] = make_float2(x, y);
    }
}

extern "C" void kernel_launch(void* const* d_in, const int* in_sizes, int n_in,
                              void* d_out, int out_size) {
    // Input order:
    // 0 roughNoh 1 anisoToh 2 nDotLV 3 tDotLV(unused) 4 metalLoh 5 subCg
    // 6 spst 7 shst 8 lumCs 9 tabRAEnc 10 tabCgEnc 11 tabRSEnc 12 tabRADec
    // 13 tabCgDec 14 tabLVR 15 tabLV 16 tabNHL
    const int n = in_sizes[0] / 2;

    static bool attr_set = false;
    if (!attr_set) {
        cudaFuncSetAttribute(disneynet_kernel,
                             cudaFuncAttributeMaxDynamicSharedMemorySize,
                             SMEM_BYTES);
        attr_set = true;
    }

    const int threads = 1024;
    const int blocks = 148;  // one persistent wave (1 CTA/SM with 145KB smem)
    disneynet_kernel<<<blocks, threads, SMEM_BYTES>>>(
        (const float2*)d_in[0],
        (const float2*)d_in[1],
        (const float2*)d_in[2],
        (const float2*)d_in[4],
        (const float2*)d_in[5],
        (const float2*)d_in[6],
        (const float2*)d_in[7],
        (const float2*)d_in[8],
        (const float2*)d_in[9],
        (const float*)d_in[10],
        (const float*)d_in[11],
        (const float*)d_in[12],
        (const float2*)d_in[13],
        (const float*)d_in[14],
        (const float4*)d_in[15],
        (const float4*)d_in[16],
        (float2*)d_out,
        n);
}

// round 3
// speedup vs baseline: 1.5834x; 1.1039x over previous
#include <cuda_runtime.h>
#include <cuda_fp16.h>
#include <math.h>

// DisneyNet: pointwise shading eval with table gathers.
// Persistent kernel; small LUTs staged into smem, value-only tables in fp16
// to cut smem-crossbar bytes (the measured bottleneck).

static __device__ __forceinline__ float triw(float x) {
    return 2.0f * fabsf(0.5f * x - floorf(0.5f * x + 0.5f));
}

static __device__ __forceinline__ float clip01(float x) {
    return fminf(fmaxf(x, 0.0f), 1.0f - 1e-6f);
}

// ---- shared memory layout (in floats) ----
// sRS   : 64x64 half4  -> 8192 floats   (triw-applied, ch3 pad)
// sLV   : 32x32 half4  -> 2048 floats   (triw-applied)
// sNHL  : 32x32 half4  -> 2048 floats   (triw-applied)
// sRA01 : 48x48 float2 -> 4608 floats   (fp32, feeds den^2)
// sRA2  : 48x48 float  -> 2304 floats
// sLVR  : 32x32 float  -> 1024 floats   (triw-applied)
// sCgE  : 2048 float   -> 2048 floats   (triw-applied; coordinate -> fp32)
// sCgD  : 96 float2    ->  192 floats
static constexpr int OFF_RS   = 0;
static constexpr int OFF_LV   = OFF_RS   + 8192;
static constexpr int OFF_NHL  = OFF_LV   + 2048;
static constexpr int OFF_RA01 = OFF_NHL  + 2048;
static constexpr int OFF_RA2  = OFF_RA01 + 4608;
static constexpr int OFF_LVR  = OFF_RA2  + 2304;
static constexpr int OFF_CGE  = OFF_LVR  + 1024;
static constexpr int OFF_CGD  = OFF_CGE  + 2048;
static constexpr int SMEM_FLOATS = OFF_CGD + 192;
static constexpr int SMEM_BYTES  = SMEM_FLOATS * 4;   // 89856 B

// Compute bilinear setup: indices + weights. clip01 guarantees u0+1 <= U-1.
struct Bl { int i00, i10, i01, i11; float w00, w10, w01, w11; };
template <int U, int V>
static __device__ __forceinline__ Bl bl_setup(float cu, float cv) {
    float u = clip01(cu) * (float)(U - 1);
    float v = clip01(cv) * (float)(V - 1);
    float u0f = floorf(u), v0f = floorf(v);
    float fu = u - u0f, fv = v - v0f;
    int u0 = (int)u0f, v0 = (int)v0f;
    int base = u0 * V + v0;
    Bl b;
    b.i00 = base;     b.i10 = base + V;
    b.i01 = base + 1; b.i11 = base + V + 1;
    b.w00 = (1.0f - fu) * (1.0f - fv);
    b.w10 = fu * (1.0f - fv);
    b.w01 = (1.0f - fu) * fv;
    b.w11 = fu * fv;
    return b;
}

// fp16 half4 corner fetch (one LDS.64) -> float4
static __device__ __forceinline__ float4 ld_h4(const uint2* __restrict__ s, int idx) {
    uint2 r = s[idx];
    __half2 h01 = *reinterpret_cast<__half2*>(&r.x);
    __half2 h23 = *reinterpret_cast<__half2*>(&r.y);
    float2 f01 = __half22float2(h01);
    float2 f23 = __half22float2(h23);
    return make_float4(f01.x, f01.y, f23.x, f23.y);
}

template <int U, int V>
static __device__ __forceinline__ float4 bilin_h4(const uint2* __restrict__ s,
                                                  float cu, float cv) {
    Bl b = bl_setup<U, V>(cu, cv);
    float4 a = ld_h4(s, b.i00);
    float4 c = ld_h4(s, b.i10);
    float4 d = ld_h4(s, b.i01);
    float4 e = ld_h4(s, b.i11);
    float4 o;
    o.x = a.x * b.w00 + c.x * b.w10 + d.x * b.w01 + e.x * b.w11;
    o.y = a.y * b.w00 + c.y * b.w10 + d.y * b.w01 + e.y * b.w11;
    o.z = a.z * b.w00 + c.z * b.w10 + d.z * b.w01 + e.z * b.w11;
    o.w = a.w * b.w00 + c.w * b.w10 + d.w * b.w01 + e.w * b.w11;
    return o;
}

__global__ void __launch_bounds__(512, 2)
disneynet_kernel(const float2* __restrict__ roughNoh,
                 const float2* __restrict__ anisoToh,
                 const float2* __restrict__ nDotLV,
                 const float2* __restrict__ metalLoh,
                 const float2* __restrict__ subCg,
                 const float2* __restrict__ spst,
                 const float2* __restrict__ shst,
                 const float2* __restrict__ lumCs,
                 const float2* __restrict__ tabRAEnc,  // 2048x2048x2 (global/L2)
                 const float*  __restrict__ tabCgEnc,  // 2048
                 const float*  __restrict__ tabRSEnc,  // 64x64x3
                 const float*  __restrict__ tabRADec,  // 48x48x3
                 const float2* __restrict__ tabCgDec,  // 96x2
                 const float*  __restrict__ tabLVR,    // 32x32
                 const float4* __restrict__ tabLV,     // 32x32x4
                 const float4* __restrict__ tabNHL,    // 32x32x4
                 float2* __restrict__ out,
                 int n) {
    extern __shared__ float smem[];
    uint2*  sRS   = (uint2*)(smem + OFF_RS);
    uint2*  sLV   = (uint2*)(smem + OFF_LV);
    uint2*  sNHL  = (uint2*)(smem + OFF_NHL);
    float2* sRA01 = (float2*)(smem + OFF_RA01);
    float*  sRA2  = smem + OFF_RA2;
    float*  sLVR  = smem + OFF_LVR;
    float*  sCgE  = smem + OFF_CGE;
    float2* sCgD  = (float2*)(smem + OFF_CGD);

    const int tid = threadIdx.x;
    const int nthr = blockDim.x;

    // ---- stage tables ----
    for (int idx = tid; idx < 64 * 64; idx += nthr) {
        const float* src = tabRSEnc + idx * 3;
        __half2 h01 = __floats2half2_rn(triw(src[0]), triw(src[1]));
        __half2 h23 = __floats2half2_rn(triw(src[2]), 0.0f);
        uint2 r;
        r.x = *reinterpret_cast<unsigned*>(&h01);
        r.y = *reinterpret_cast<unsigned*>(&h23);
        sRS[idx] = r;
    }
    for (int idx = tid; idx < 32 * 32; idx += nthr) {
        float4 v = tabLV[idx];
        __half2 a = __floats2half2_rn(triw(v.x), triw(v.y));
        __half2 b = __floats2half2_rn(triw(v.z), triw(v.w));
        uint2 r;
        r.x = *reinterpret_cast<unsigned*>(&a);
        r.y = *reinterpret_cast<unsigned*>(&b);
        sLV[idx] = r;
        float4 w = tabNHL[idx];
        __half2 c = __floats2half2_rn(triw(w.x), triw(w.y));
        __half2 d = __floats2half2_rn(triw(w.z), triw(w.w));
        uint2 q;
        q.x = *reinterpret_cast<unsigned*>(&c);
        q.y = *reinterpret_cast<unsigned*>(&d);
        sNHL[idx] = q;
        sLVR[idx] = triw(tabLVR[idx]);
    }
    for (int idx = tid; idx < 48 * 48; idx += nthr) {
        const float* src = tabRADec + idx * 3;
        sRA01[idx] = make_float2(src[0], src[1]);
        sRA2[idx]  = src[2];
    }
    for (int idx = tid; idx < 2048; idx += nthr) {
        sCgE[idx] = triw(tabCgEnc[idx]);
    }
    for (int idx = tid; idx < 96; idx += nthr) {
        sCgD[idx] = tabCgDec[idx];
    }
    __syncthreads();

    const int stride = gridDim.x * nthr;
    for (int i = blockIdx.x * nthr + tid; i < n; i += stride) {
        const float2 rn = roughNoh[i];
        const float2 at = anisoToh[i];
        const float2 nl = nDotLV[i];
        const float2 ml = metalLoh[i];
        const float2 sc = subCg[i];
        const float2 sp = spst[i];
        const float2 sh = shst[i];
        const float2 lc = lumCs[i];

        // ra = nearest, normalized, tabRAEnc (global, L2-resident)
        int ui = (int)rintf(clip01(rn.x) * 2047.0f);
        int vi = (int)rintf(clip01(at.x) * 2047.0f);
        float2 raRaw = __ldg(tabRAEnc + (ui * 2048 + vi));
        float ra0 = triw(raRaw.x);
        float ra1 = triw(raRaw.y);

        // cg = nearest (pre-normalized)
        int ci = (int)rintf(clip01(sc.y) * 2047.0f);
        float cg0 = sCgE[ci];

        // rsEnc = bilinear (pre-normalized, fp16 values)
        float4 rs = bilin_h4<64, 64>(sRS, rn.x, sc.x);

        const float m = ml.x;
        const float om = 1.0f - m;
        const float cd  = om * lc.x;
        const float cm0 = sp.x * 0.1f * om * sp.y + m * lc.x;
        const float cm1 = sp.x * 0.1f * om * (1.0f - sp.y);
        const float cs0 = sh.x * om * sh.y;
        const float cs1 = sh.x * om * (1.0f - sh.y);
        const float ccv = 0.0625f * lc.y;

        const float rsCd0 = rs.x * cd;
        const float rsCd1 = rs.y * cd;
        const float rsCd2 = rs.z * cd;

        // raCoefs = bilinear, fp32 SoA (feeds den^2)
        float raC0, raC1, raC2;
        {
            Bl b = bl_setup<48, 48>(ra0, ra1);
            float2 a = sRA01[b.i00];
            float2 c = sRA01[b.i10];
            float2 d = sRA01[b.i01];
            float2 e = sRA01[b.i11];
            raC0 = a.x * b.w00 + c.x * b.w10 + d.x * b.w01 + e.x * b.w11;
            raC1 = a.y * b.w00 + c.y * b.w10 + d.y * b.w01 + e.y * b.w11;
            raC2 = sRA2[b.i00] * b.w00 + sRA2[b.i10] * b.w10
                 + sRA2[b.i01] * b.w01 + sRA2[b.i11] * b.w11;
        }

        // cgCoefs = 1D bilinear, fp32
        float cgC0, cgC1;
        {
            float u = clip01(cg0) * 95.0f;
            float u0f = floorf(u);
            float fu = u - u0f;
            int u0 = (int)u0f;
            float2 a = sCgD[u0];
            float2 b = sCgD[u0 + 1];
            cgC0 = a.x + (b.x - a.x) * fu;
            cgC1 = a.y + (b.y - a.y) * fu;
        }

        // vTerm = bilinear, fp32 scalar table
        float vT;
        {
            Bl b = bl_setup<32, 32>(nl.x * nl.y, ra0);
            vT = sLVR[b.i00] * b.w00 + sLVR[b.i10] * b.w10
               + sLVR[b.i01] * b.w01 + sLVR[b.i11] * b.w11;
        }

        // nlvCoefs / nhlCoefs (fp16 values)
        float4 nlv = bilin_h4<32, 32>(sLV, nl.x, nl.y);
        float4 nhl = bilin_h4<32, 32>(sNHL, ml.y, nl.x);

        const float noh2 = rn.y * rn.y;
        const float den = raC0 * at.y * at.y + raC1 * noh2 + raC2;
        const float dT = __fdividef(0.25f, nl.y * den * den);

        float x = rsCd0 * ml.y * nlv.y
                + rsCd1 * nlv.z
                + rsCd2 * nlv.w
                + cm0 * vT * nhl.z * dT
                + cs0 * nhl.x;

        float y = ((1.0f - cm1) * nhl.w + cm1) * vT * dT
                + cs1 * nhl.x
                + ccv * nhl.y * nlv.x * __fdividef(1.0f, nl.y * (cgC0 * noh2 + cgC1));

        out[i] = make_float2(x, y);
    }
}

extern "C" void kernel_launch(void* const* d_in, const int* in_sizes, int n_in,
                              void* d_out, int out_size) {
    // Input order:
    // 0 roughNoh 1 anisoToh 2 nDotLV 3 tDotLV(unused) 4 metalLoh 5 subCg
    // 6 spst 7 shst 8 lumCs 9 tabRAEnc 10 tabCgEnc 11 tabRSEnc 12 tabRADec
    // 13 tabCgDec 14 tabLVR 15 tabLV 16 tabNHL
    const int n = in_sizes[0] / 2;

    static bool attr_set = false;
    if (!attr_set) {
        cudaFuncSetAttribute(disneynet_kernel,
                             cudaFuncAttributeMaxDynamicSharedMemorySize,
                             SMEM_BYTES);
        attr_set = true;
    }

    const int threads = 512;
    const int blocks = 296;  // 2 CTAs/SM x 148 SMs, persistent
    disneynet_kernel<<<blocks, threads, SMEM_BYTES>>>(
        (const float2*)d_in[0],
        (const float2*)d_in[1],
        (const float2*)d_in[2],
        (const float2*)d_in[4],
        (const float2*)d_in[5],
        (const float2*)d_in[6],
        (const float2*)d_in[7],
        (const float2*)d_in[8],
        (const float2*)d_in[9],
        (const float*)d_in[10],
        (const float*)d_in[11],
        (const float*)d_in[12],
        (const float2*)d_in[13],
        (const float*)d_in[14],
        (const float4*)d_in[15],
        (const float4*)d_in[16],
        (float2*)d_out,
        n);
}

// round 4
// speedup vs baseline: 1.7006x; 1.0740x over previous
#include <cuda_runtime.h>
#include <cuda_fp16.h>
#include <math.h>

// DisneyNet: pointwise shading eval with table gathers.
// Persistent kernel; small LUTs in smem (fp16 where precision allows),
// big tabRAEnc gather software-pipelined one iteration ahead to hide
// its L2 latency (the measured critical-path stall).

static __device__ __forceinline__ float triw(float x) {
    return 2.0f * fabsf(0.5f * x - floorf(0.5f * x + 0.5f));
}

static __device__ __forceinline__ float clip01(float x) {
    return fminf(fmaxf(x, 0.0f), 1.0f - 1e-6f);
}

// ---- shared memory layout (in floats) ----
static constexpr int OFF_RS   = 0;                  // 64x64 half4 (triw) -> 8192
static constexpr int OFF_LV   = OFF_RS   + 8192;    // 32x32 half4 (triw) -> 2048
static constexpr int OFF_NHL  = OFF_LV   + 2048;    // 32x32 half4 (triw) -> 2048
static constexpr int OFF_RA01 = OFF_NHL  + 2048;    // 48x48 float2       -> 4608
static constexpr int OFF_RA2  = OFF_RA01 + 4608;    // 48x48 float        -> 2304
static constexpr int OFF_LVR  = OFF_RA2  + 2304;    // 32x32 float (triw) -> 1024
static constexpr int OFF_CGE  = OFF_LVR  + 1024;    // 2048 float (triw)  -> 2048
static constexpr int OFF_CGD  = OFF_CGE  + 2048;    // 96 float2          ->  192
static constexpr int SMEM_FLOATS = OFF_CGD + 192;
static constexpr int SMEM_BYTES  = SMEM_FLOATS * 4;   // 89856 B

struct Bl { int i00, i10, i01, i11; float w00, w10, w01, w11; };
template <int U, int V>
static __device__ __forceinline__ Bl bl_setup(float cu, float cv) {
    float u = clip01(cu) * (float)(U - 1);
    float v = clip01(cv) * (float)(V - 1);
    float u0f = floorf(u), v0f = floorf(v);
    float fu = u - u0f, fv = v - v0f;
    int u0 = (int)u0f, v0 = (int)v0f;
    int base = u0 * V + v0;
    Bl b;
    b.i00 = base;     b.i10 = base + V;
    b.i01 = base + 1; b.i11 = base + V + 1;
    b.w00 = (1.0f - fu) * (1.0f - fv);
    b.w10 = fu * (1.0f - fv);
    b.w01 = (1.0f - fu) * fv;
    b.w11 = fu * fv;
    return b;
}

static __device__ __forceinline__ float4 ld_h4(const uint2* __restrict__ s, int idx) {
    uint2 r = s[idx];
    __half2 h01 = *reinterpret_cast<__half2*>(&r.x);
    __half2 h23 = *reinterpret_cast<__half2*>(&r.y);
    float2 f01 = __half22float2(h01);
    float2 f23 = __half22float2(h23);
    return make_float4(f01.x, f01.y, f23.x, f23.y);
}

template <int U, int V>
static __device__ __forceinline__ float4 bilin_h4(const uint2* __restrict__ s,
                                                  float cu, float cv) {
    Bl b = bl_setup<U, V>(cu, cv);
    float4 a = ld_h4(s, b.i00);
    float4 c = ld_h4(s, b.i10);
    float4 d = ld_h4(s, b.i01);
    float4 e = ld_h4(s, b.i11);
    float4 o;
    o.x = a.x * b.w00 + c.x * b.w10 + d.x * b.w01 + e.x * b.w11;
    o.y = a.y * b.w00 + c.y * b.w10 + d.y * b.w01 + e.y * b.w11;
    o.z = a.z * b.w00 + c.z * b.w10 + d.z * b.w01 + e.z * b.w11;
    o.w = a.w * b.w00 + c.w * b.w10 + d.w * b.w01 + e.w * b.w11;
    return o;
}

static __device__ __forceinline__ float2 gather_ra(const float2* __restrict__ t,
                                                   float rx, float ax) {
    int ui = (int)rintf(clip01(rx) * 2047.0f);
    int vi = (int)rintf(clip01(ax) * 2047.0f);
    return __ldg(t + (ui * 2048 + vi));
}

__global__ void __launch_bounds__(512, 2)
disneynet_kernel(const float2* __restrict__ roughNoh,
                 const float2* __restrict__ anisoToh,
                 const float2* __restrict__ nDotLV,
                 const float2* __restrict__ metalLoh,
                 const float2* __restrict__ subCg,
                 const float2* __restrict__ spst,
                 const float2* __restrict__ shst,
                 const float2* __restrict__ lumCs,
                 const float2* __restrict__ tabRAEnc,  // 2048x2048x2 (global/L2)
                 const float*  __restrict__ tabCgEnc,  // 2048
                 const float*  __restrict__ tabRSEnc,  // 64x64x3
                 const float*  __restrict__ tabRADec,  // 48x48x3
                 const float2* __restrict__ tabCgDec,  // 96x2
                 const float*  __restrict__ tabLVR,    // 32x32
                 const float4* __restrict__ tabLV,     // 32x32x4
                 const float4* __restrict__ tabNHL,    // 32x32x4
                 float2* __restrict__ out,
                 int n) {
    extern __shared__ float smem[];
    uint2*  sRS   = (uint2*)(smem + OFF_RS);
    uint2*  sLV   = (uint2*)(smem + OFF_LV);
    uint2*  sNHL  = (uint2*)(smem + OFF_NHL);
    float2* sRA01 = (float2*)(smem + OFF_RA01);
    float*  sRA2  = smem + OFF_RA2;
    float*  sLVR  = smem + OFF_LVR;
    float*  sCgE  = smem + OFF_CGE;
    float2* sCgD  = (float2*)(smem + OFF_CGD);

    const int tid = threadIdx.x;
    const int nthr = blockDim.x;

    // ---- stage tables ----
    for (int idx = tid; idx < 64 * 64; idx += nthr) {
        const float* src = tabRSEnc + idx * 3;
        __half2 h01 = __floats2half2_rn(triw(src[0]), triw(src[1]));
        __half2 h23 = __floats2half2_rn(triw(src[2]), 0.0f);
        uint2 r;
        r.x = *reinterpret_cast<unsigned*>(&h01);
        r.y = *reinterpret_cast<unsigned*>(&h23);
        sRS[idx] = r;
    }
    for (int idx = tid; idx < 32 * 32; idx += nthr) {
        float4 v = tabLV[idx];
        __half2 a = __floats2half2_rn(triw(v.x), triw(v.y));
        __half2 b = __floats2half2_rn(triw(v.z), triw(v.w));
        uint2 r;
        r.x = *reinterpret_cast<unsigned*>(&a);
        r.y = *reinterpret_cast<unsigned*>(&b);
        sLV[idx] = r;
        float4 w = tabNHL[idx];
        __half2 c = __floats2half2_rn(triw(w.x), triw(w.y));
        __half2 d = __floats2half2_rn(triw(w.z), triw(w.w));
        uint2 q;
        q.x = *reinterpret_cast<unsigned*>(&c);
        q.y = *reinterpret_cast<unsigned*>(&d);
        sNHL[idx] = q;
        sLVR[idx] = triw(tabLVR[idx]);
    }
    for (int idx = tid; idx < 48 * 48; idx += nthr) {
        const float* src = tabRADec + idx * 3;
        sRA01[idx] = make_float2(src[0], src[1]);
        sRA2[idx]  = src[2];
    }
    for (int idx = tid; idx < 2048; idx += nthr) {
        sCgE[idx] = triw(tabCgEnc[idx]);
    }
    for (int idx = tid; idx < 96; idx += nthr) {
        sCgD[idx] = tabCgDec[idx];
    }
    __syncthreads();

    const int stride = gridDim.x * nthr;
    const int i0 = blockIdx.x * nthr + tid;

    // Prologue: issue first iteration's gather + index streams.
    float2 rn, at, raRaw;
    if (i0 < n) {
        rn = roughNoh[i0];
        at = anisoToh[i0];
        raRaw = gather_ra(tabRAEnc, rn.x, at.x);
    }

    for (int i = i0; i < n; i += stride) {
        // Prefetch next iteration's gather (hides L2 latency behind this body).
        const int j = i + stride;
        float2 rn_n, at_n, raRaw_n;
        if (j < n) {
            rn_n = roughNoh[j];
            at_n = anisoToh[j];
            raRaw_n = gather_ra(tabRAEnc, rn_n.x, at_n.x);
        }

        const float2 nl = nDotLV[i];
        const float2 ml = metalLoh[i];
        const float2 sc = subCg[i];
        const float2 sp = spst[i];
        const float2 sh = shst[i];
        const float2 lc = lumCs[i];

        const float ra0 = triw(raRaw.x);
        const float ra1 = triw(raRaw.y);

        // cg = nearest (pre-normalized)
        int ci = (int)rintf(clip01(sc.y) * 2047.0f);
        float cg0 = sCgE[ci];

        // rsEnc = bilinear (pre-normalized, fp16 values)
        float4 rs = bilin_h4<64, 64>(sRS, rn.x, sc.x);

        const float m = ml.x;
        const float om = 1.0f - m;
        const float cd  = om * lc.x;
        const float cm0 = sp.x * 0.1f * om * sp.y + m * lc.x;
        const float cm1 = sp.x * 0.1f * om * (1.0f - sp.y);
        const float cs0 = sh.x * om * sh.y;
        const float cs1 = sh.x * om * (1.0f - sh.y);
        const float ccv = 0.0625f * lc.y;

        const float rsCd0 = rs.x * cd;
        const float rsCd1 = rs.y * cd;
        const float rsCd2 = rs.z * cd;

        // raCoefs = bilinear, fp32 SoA (feeds den^2)
        float raC0, raC1, raC2;
        {
            Bl b = bl_setup<48, 48>(ra0, ra1);
            float2 a = sRA01[b.i00];
            float2 c = sRA01[b.i10];
            float2 d = sRA01[b.i01];
            float2 e = sRA01[b.i11];
            raC0 = a.x * b.w00 + c.x * b.w10 + d.x * b.w01 + e.x * b.w11;
            raC1 = a.y * b.w00 + c.y * b.w10 + d.y * b.w01 + e.y * b.w11;
            raC2 = sRA2[b.i00] * b.w00 + sRA2[b.i10] * b.w10
                 + sRA2[b.i01] * b.w01 + sRA2[b.i11] * b.w11;
        }

        // cgCoefs = 1D bilinear, fp32
        float cgC0, cgC1;
        {
            float u = clip01(cg0) * 95.0f;
            float u0f = floorf(u);
            float fu = u - u0f;
            int u0 = (int)u0f;
            float2 a = sCgD[u0];
            float2 b = sCgD[u0 + 1];
            cgC0 = a.x + (b.x - a.x) * fu;
            cgC1 = a.y + (b.y - a.y) * fu;
        }

        // vTerm = bilinear, fp32 scalar table
        float vT;
        {
            Bl b = bl_setup<32, 32>(nl.x * nl.y, ra0);
            vT = sLVR[b.i00] * b.w00 + sLVR[b.i10] * b.w10
               + sLVR[b.i01] * b.w01 + sLVR[b.i11] * b.w11;
        }

        // nlvCoefs / nhlCoefs (fp16 values)
        float4 nlv = bilin_h4<32, 32>(sLV, nl.x, nl.y);
        float4 nhl = bilin_h4<32, 32>(sNHL, ml.y, nl.x);

        const float noh2 = rn.y * rn.y;
        const float den = raC0 * at.y * at.y + raC1 * noh2 + raC2;
        const float dT = __fdividef(0.25f, nl.y * den * den);

        float x = rsCd0 * ml.y * nlv.y
                + rsCd1 * nlv.z
                + rsCd2 * nlv.w
                + cm0 * vT * nhl.z * dT
                + cs0 * nhl.x;

        float y = ((1.0f - cm1) * nhl.w + cm1) * vT * dT
                + cs1 * nhl.x
                + ccv * nhl.y * nlv.x * __fdividef(1.0f, nl.y * (cgC0 * noh2 + cgC1));

        out[i] = make_float2(x, y);

        // rotate pipeline
        rn = rn_n;
        at = at_n;
        raRaw = raRaw_n;
    }
}

extern "C" void kernel_launch(void* const* d_in, const int* in_sizes, int n_in,
                              void* d_out, int out_size) {
    // Input order:
    // 0 roughNoh 1 anisoToh 2 nDotLV 3 tDotLV(unused) 4 metalLoh 5 subCg
    // 6 spst 7 shst 8 lumCs 9 tabRAEnc 10 tabCgEnc 11 tabRSEnc 12 tabRADec
    // 13 tabCgDec 14 tabLVR 15 tabLV 16 tabNHL
    const int n = in_sizes[0] / 2;

    static bool attr_set = false;
    if (!attr_set) {
        cudaFuncSetAttribute(disneynet_kernel,
                             cudaFuncAttributeMaxDynamicSharedMemorySize,
                             SMEM_BYTES);
        attr_set = true;
    }

    const int threads = 512;
    const int blocks = 296;  // 2 CTAs/SM x 148 SMs, persistent
    disneynet_kernel<<<blocks, threads, SMEM_BYTES>>>(
        (const float2*)d_in[0],
        (const float2*)d_in[1],
        (const float2*)d_in[2],
        (const float2*)d_in[4],
        (const float2*)d_in[5],
        (const float2*)d_in[6],
        (const float2*)d_in[7],
        (const float2*)d_in[8],
        (const float2*)d_in[9],
        (const float*)d_in[10],
        (const float*)d_in[11],
        (const float*)d_in[12],
        (const float2*)d_in[13],
        (const float*)d_in[14],
        (const float4*)d_in[15],
        (const float4*)d_in[16],
        (float2*)d_out,
        n);
}

// round 5
// speedup vs baseline: 1.8228x; 1.0719x over previous
#include <cuda_runtime.h>
#include <cuda_fp16.h>
#include <math.h>

// DisneyNet: pointwise shading eval with table gathers.
// Persistent kernel; small LUTs in smem (fp16 where safe), cg lookup chain
// pre-fused into one table, tabRAEnc gather software-pipelined, streaming
// cache hints to keep tabRAEnc L2-resident.

static __device__ __forceinline__ float triw(float x) {
    return 2.0f * fabsf(0.5f * x - floorf(0.5f * x + 0.5f));
}

static __device__ __forceinline__ float clip01(float x) {
    return fminf(fmaxf(x, 0.0f), 1.0f - 1e-6f);
}

// ---- shared memory layout (in floats) ----
static constexpr int OFF_RS   = 0;                  // 64x64 half4 (triw) -> 8192
static constexpr int OFF_LV   = OFF_RS   + 8192;    // 32x32 half4 (triw) -> 2048
static constexpr int OFF_NHL  = OFF_LV   + 2048;    // 32x32 half4 (triw) -> 2048
static constexpr int OFF_RA01 = OFF_NHL  + 2048;    // 48x48 float2       -> 4608
static constexpr int OFF_RA2  = OFF_RA01 + 4608;    // 48x48 float        -> 2304
static constexpr int OFF_LVR  = OFF_RA2  + 2304;    // 32x32 half (triw)  ->  512
static constexpr int OFF_CGF  = OFF_LVR  + 512;     // 2048 float2 fused  -> 4096
static constexpr int SMEM_FLOATS = OFF_CGF + 4096;
static constexpr int SMEM_BYTES  = SMEM_FLOATS * 4;   // 95232 B

struct Bl { int i00, i10, i01, i11; float w00, w10, w01, w11; };
template <int U, int V>
static __device__ __forceinline__ Bl bl_setup(float cu, float cv) {
    float u = clip01(cu) * (float)(U - 1);
    float v = clip01(cv) * (float)(V - 1);
    float u0f = floorf(u), v0f = floorf(v);
    float fu = u - u0f, fv = v - v0f;
    int u0 = (int)u0f, v0 = (int)v0f;
    int base = u0 * V + v0;
    Bl b;
    b.i00 = base;     b.i10 = base + V;
    b.i01 = base + 1; b.i11 = base + V + 1;
    b.w00 = (1.0f - fu) * (1.0f - fv);
    b.w10 = fu * (1.0f - fv);
    b.w01 = (1.0f - fu) * fv;
    b.w11 = fu * fv;
    return b;
}

static __device__ __forceinline__ float4 ld_h4(const uint2* __restrict__ s, int idx) {
    uint2 r = s[idx];
    __half2 h01 = *reinterpret_cast<__half2*>(&r.x);
    __half2 h23 = *reinterpret_cast<__half2*>(&r.y);
    float2 f01 = __half22float2(h01);
    float2 f23 = __half22float2(h23);
    return make_float4(f01.x, f01.y, f23.x, f23.y);
}

template <int U, int V>
static __device__ __forceinline__ float4 bilin_h4(const uint2* __restrict__ s,
                                                  float cu, float cv) {
    Bl b = bl_setup<U, V>(cu, cv);
    float4 a = ld_h4(s, b.i00);
    float4 c = ld_h4(s, b.i10);
    float4 d = ld_h4(s, b.i01);
    float4 e = ld_h4(s, b.i11);
    float4 o;
    o.x = a.x * b.w00 + c.x * b.w10 + d.x * b.w01 + e.x * b.w11;
    o.y = a.y * b.w00 + c.y * b.w10 + d.y * b.w01 + e.y * b.w11;
    o.z = a.z * b.w00 + c.z * b.w10 + d.z * b.w01 + e.z * b.w11;
    o.w = a.w * b.w00 + c.w * b.w10 + d.w * b.w01 + e.w * b.w11;
    return o;
}

static __device__ __forceinline__ float2 gather_ra(const float2* __restrict__ t,
                                                   float rx, float ax) {
    int ui = (int)rintf(clip01(rx) * 2047.0f);
    int vi = (int)rintf(clip01(ax) * 2047.0f);
    return __ldg(t + (ui * 2048 + vi));
}

static __device__ __forceinline__ float2 ldcs2(const float2* p) {
    return __ldcs(p);
}

__global__ void __launch_bounds__(512, 2)
disneynet_kernel(const float2* __restrict__ roughNoh,
                 const float2* __restrict__ anisoToh,
                 const float2* __restrict__ nDotLV,
                 const float2* __restrict__ metalLoh,
                 const float2* __restrict__ subCg,
                 const float2* __restrict__ spst,
                 const float2* __restrict__ shst,
                 const float2* __restrict__ lumCs,
                 const float2* __restrict__ tabRAEnc,  // 2048x2048x2 (global/L2)
                 const float*  __restrict__ tabCgEnc,  // 2048
                 const float*  __restrict__ tabRSEnc,  // 64x64x3
                 const float*  __restrict__ tabRADec,  // 48x48x3
                 const float2* __restrict__ tabCgDec,  // 96x2
                 const float*  __restrict__ tabLVR,    // 32x32
                 const float4* __restrict__ tabLV,     // 32x32x4
                 const float4* __restrict__ tabNHL,    // 32x32x4
                 float2* __restrict__ out,
                 int n) {
    extern __shared__ float smem[];
    uint2*  sRS   = (uint2*)(smem + OFF_RS);
    uint2*  sLV   = (uint2*)(smem + OFF_LV);
    uint2*  sNHL  = (uint2*)(smem + OFF_NHL);
    float2* sRA01 = (float2*)(smem + OFF_RA01);
    float*  sRA2  = smem + OFF_RA2;
    __half* sLVR  = (__half*)(smem + OFF_LVR);
    float2* sCgF  = (float2*)(smem + OFF_CGF);

    const int tid = threadIdx.x;
    const int nthr = blockDim.x;

    // ---- stage tables ----
    for (int idx = tid; idx < 64 * 64; idx += nthr) {
        const float* src = tabRSEnc + idx * 3;
        __half2 h01 = __floats2half2_rn(triw(src[0]), triw(src[1]));
        __half2 h23 = __floats2half2_rn(triw(src[2]), 0.0f);
        uint2 r;
        r.x = *reinterpret_cast<unsigned*>(&h01);
        r.y = *reinterpret_cast<unsigned*>(&h23);
        sRS[idx] = r;
    }
    for (int idx = tid; idx < 32 * 32; idx += nthr) {
        float4 v = tabLV[idx];
        __half2 a = __floats2half2_rn(triw(v.x), triw(v.y));
        __half2 b = __floats2half2_rn(triw(v.z), triw(v.w));
        uint2 r;
        r.x = *reinterpret_cast<unsigned*>(&a);
        r.y = *reinterpret_cast<unsigned*>(&b);
        sLV[idx] = r;
        float4 w = tabNHL[idx];
        __half2 c = __floats2half2_rn(triw(w.x), triw(w.y));
        __half2 d = __floats2half2_rn(triw(w.z), triw(w.w));
        uint2 q;
        q.x = *reinterpret_cast<unsigned*>(&c);
        q.y = *reinterpret_cast<unsigned*>(&d);
        sNHL[idx] = q;
        sLVR[idx] = __float2half_rn(triw(tabLVR[idx]));
    }
    for (int idx = tid; idx < 48 * 48; idx += nthr) {
        const float* src = tabRADec + idx * 3;
        sRA01[idx] = make_float2(src[0], src[1]);
        sRA2[idx]  = src[2];
    }
    // Fused cg chain: ci -> triw(tabCgEnc[ci]) -> bilinear(tabCgDec).
    // Same arithmetic as the reference, folded into one table.
    for (int idx = tid; idx < 2048; idx += nthr) {
        float cg0 = triw(tabCgEnc[idx]);
        float u = clip01(cg0) * 95.0f;
        float u0f = floorf(u);
        float fu = u - u0f;
        int u0 = (int)u0f;
        int u1 = min(u0 + 1, 95);
        float2 a = tabCgDec[u0];
        float2 b = tabCgDec[u1];
        sCgF[idx] = make_float2(a.x * (1.0f - fu) + b.x * fu,
                                a.y * (1.0f - fu) + b.y * fu);
    }
    __syncthreads();

    const int stride = gridDim.x * nthr;
    const int i0 = blockIdx.x * nthr + tid;

    // Prologue: first iteration's gather.
    float2 rn, at, raRaw;
    if (i0 < n) {
        rn = ldcs2(roughNoh + i0);
        at = ldcs2(anisoToh + i0);
        raRaw = gather_ra(tabRAEnc, rn.x, at.x);
    }

    for (int i = i0; i < n; i += stride) {
        // Prefetch next iteration's gather (hides L2 latency behind this body).
        const int j = i + stride;
        float2 rn_n, at_n, raRaw_n;
        if (j < n) {
            rn_n = ldcs2(roughNoh + j);
            at_n = ldcs2(anisoToh + j);
            raRaw_n = gather_ra(tabRAEnc, rn_n.x, at_n.x);
        }

        const float2 nl = ldcs2(nDotLV + i);
        const float2 ml = ldcs2(metalLoh + i);
        const float2 sc = ldcs2(subCg + i);
        const float2 sp = ldcs2(spst + i);
        const float2 sh = ldcs2(shst + i);
        const float2 lc = ldcs2(lumCs + i);

        const float ra0 = triw(raRaw.x);
        const float ra1 = triw(raRaw.y);

        // fused cg -> (cgC0, cgC1)
        int ci = (int)rintf(clip01(sc.y) * 2047.0f);
        float2 cgC = sCgF[ci];

        // rsEnc = bilinear (pre-normalized, fp16 values)
        float4 rs = bilin_h4<64, 64>(sRS, rn.x, sc.x);

        const float m = ml.x;
        const float om = 1.0f - m;
        const float cd  = om * lc.x;
        const float cm0 = sp.x * 0.1f * om * sp.y + m * lc.x;
        const float cm1 = sp.x * 0.1f * om * (1.0f - sp.y);
        const float cs0 = sh.x * om * sh.y;
        const float cs1 = sh.x * om * (1.0f - sh.y);
        const float ccv = 0.0625f * lc.y;

        const float rsCd0 = rs.x * cd;
        const float rsCd1 = rs.y * cd;
        const float rsCd2 = rs.z * cd;

        // raCoefs = bilinear, fp32 SoA (feeds den^2)
        float raC0, raC1, raC2;
        {
            Bl b = bl_setup<48, 48>(ra0, ra1);
            float2 a = sRA01[b.i00];
            float2 c = sRA01[b.i10];
            float2 d = sRA01[b.i01];
            float2 e = sRA01[b.i11];
            raC0 = a.x * b.w00 + c.x * b.w10 + d.x * b.w01 + e.x * b.w11;
            raC1 = a.y * b.w00 + c.y * b.w10 + d.y * b.w01 + e.y * b.w11;
            raC2 = sRA2[b.i00] * b.w00 + sRA2[b.i10] * b.w10
                 + sRA2[b.i01] * b.w01 + sRA2[b.i11] * b.w11;
        }

        // vTerm = bilinear, fp16 scalar table
        float vT;
        {
            Bl b = bl_setup<32, 32>(nl.x * nl.y, ra0);
            float a = __half2float(sLVR[b.i00]);
            float c = __half2float(sLVR[b.i10]);
            float d = __half2float(sLVR[b.i01]);
            float e = __half2float(sLVR[b.i11]);
            vT = a * b.w00 + c * b.w10 + d * b.w01 + e * b.w11;
        }

        // nlvCoefs / nhlCoefs (fp16 values)
        float4 nlv = bilin_h4<32, 32>(sLV, nl.x, nl.y);
        float4 nhl = bilin_h4<32, 32>(sNHL, ml.y, nl.x);

        const float noh2 = rn.y * rn.y;
        const float den = raC0 * at.y * at.y + raC1 * noh2 + raC2;
        const float dT = __fdividef(0.25f, nl.y * den * den);

        float x = rsCd0 * ml.y * nlv.y
                + rsCd1 * nlv.z
                + rsCd2 * nlv.w
                + cm0 * vT * nhl.z * dT
                + cs0 * nhl.x;

        float y = ((1.0f - cm1) * nhl.w + cm1) * vT * dT
                + cs1 * nhl.x
                + ccv * nhl.y * nlv.x * __fdividef(1.0f, nl.y * (cgC.x * noh2 + cgC.y));

        __stcs(out + i, make_float2(x, y));

        // rotate pipeline
        rn = rn_n;
        at = at_n;
        raRaw = raRaw_n;
    }
}

extern "C" void kernel_launch(void* const* d_in, const int* in_sizes, int n_in,
                              void* d_out, int out_size) {
    // Input order:
    // 0 roughNoh 1 anisoToh 2 nDotLV 3 tDotLV(unused) 4 metalLoh 5 subCg
    // 6 spst 7 shst 8 lumCs 9 tabRAEnc 10 tabCgEnc 11 tabRSEnc 12 tabRADec
    // 13 tabCgDec 14 tabLVR 15 tabLV 16 tabNHL
    const int n = in_sizes[0] / 2;

    static bool attr_set = false;
    if (!attr_set) {
        cudaFuncSetAttribute(disneynet_kernel,
                             cudaFuncAttributeMaxDynamicSharedMemorySize,
                             SMEM_BYTES);
        attr_set = true;
    }

    const int threads = 512;
    const int blocks = 296;  // 2 CTAs/SM x 148 SMs, persistent
    disneynet_kernel<<<blocks, threads, SMEM_BYTES>>>(
        (const float2*)d_in[0],
        (const float2*)d_in[1],
        (const float2*)d_in[2],
        (const float2*)d_in[4],
        (const float2*)d_in[5],
        (const float2*)d_in[6],
        (const float2*)d_in[7],
        (const float2*)d_in[8],
        (const float2*)d_in[9],
        (const float*)d_in[10],
        (const float*)d_in[11],
        (const float*)d_in[12],
        (const float2*)d_in[13],
        (const float*)d_in[14],
        (const float4*)d_in[15],
        (const float4*)d_in[16],
        (float2*)d_out,
        n);
}